// round 14
// baseline (speedup 1.0000x reference)
#include <cuda_runtime.h>
#include <cuda_fp16.h>
#include <cstdint>

// CliffordISTA — Round 12: R11 dataflow-flag design, oversubscribed:
// 256 CTAs x 256 threads (2 CTAs/SM) so flag-spins overlap with the
// co-resident CTA's compute. Tiles: 128 rows x 32 cols, K-split 8/4.
// Same arithmetic order as R11 -> outputs bit-identical.

#define NDIM 512
#define MDIM 256
#define BDIM 64
#define NITER 50
#define STEPF 0.01f
#define KT 64
#define NTHREADS 256
#define GRID 256
#define FWD_SPLIT 8
#define BWD_SPLIT 4
#define KRF 2048   // fwd realified K  (4*NDIM)
#define CCF 1024   // fwd out cols     (4*MDIM)
#define KRB 1024   // bwd realified K
#define CCB 2048   // bwd out cols

#define BUF_BYTES 20480          // per stage: A 16K | B(32 rows) 4K
#define SMEM_TOTAL (2 * BUF_BYTES)

// ---------------- device globals ----------------
__device__ __half g_Wf[(size_t)CCF * KRF];     // [col][k] 4MB
__device__ __half g_Wb[(size_t)CCB * KRB];     // [col][k] 4MB
__device__ __half g_X[2][128 * KRF];           // realified x, parity buffered
__device__ __half g_E[2][128 * KRB];           // realified err
__device__ float g_xs[BDIM * NDIM * 8];        // blade state (CTA-private chunks)
__device__ float g_yr[128 * CCF];              // realified y
__device__ float g_pf[2][(size_t)FWD_SPLIT * 128 * CCF];   // 2 x 4MB
__device__ float g_pb[2][(size_t)BWD_SPLIT * 128 * CCB];   // 2 x 4MB
// dataflow flags: one 128B line each
__device__ unsigned g_ff[32 * 32];             // fwd done per fwd-coltile (8/iter)
__device__ unsigned g_fe[32 * 32];             // err done per err-coltile (8/iter)
__device__ unsigned g_fb[64 * 32];             // bwd done per bwd-coltile (4/iter)
__device__ unsigned g_fu[64 * 32];             // upd done per upd-coltile (4/iter)

// ---------------- helpers ----------------
__device__ __forceinline__ uint32_t smem_u32(const void* p) {
    uint32_t a;
    asm("{ .reg .u64 t; cvta.to.shared.u64 t, %1; cvt.u32.u64 %0, t; }" : "=r"(a) : "l"(p));
    return a;
}

#define CP_ASYNC16(smem, gptr) \
    asm volatile("cp.async.cg.shared.global [%0], [%1], 16;" :: "r"(smem), "l"(gptr))
#define CP_COMMIT() asm volatile("cp.async.commit_group;" ::: "memory")
#define CP_WAIT1()  asm volatile("cp.async.wait_group 1;" ::: "memory")
#define CP_WAIT0()  asm volatile("cp.async.wait_group 0;" ::: "memory")

__device__ __forceinline__ void ldsm4(uint32_t* r, uint32_t addr) {
    asm volatile("ldmatrix.sync.aligned.m8n8.x4.shared.b16 {%0,%1,%2,%3}, [%4];"
                 : "=r"(r[0]), "=r"(r[1]), "=r"(r[2]), "=r"(r[3]) : "r"(addr));
}

__device__ __forceinline__ void mma_fp16(float* c, const uint32_t* a, uint32_t b0, uint32_t b1) {
    asm volatile(
        "mma.sync.aligned.m16n8k16.row.col.f32.f16.f16.f32 "
        "{%0,%1,%2,%3}, {%4,%5,%6,%7}, {%8,%9}, {%0,%1,%2,%3};"
        : "+f"(c[0]), "+f"(c[1]), "+f"(c[2]), "+f"(c[3])
        : "r"(a[0]), "r"(a[1]), "r"(a[2]), "r"(a[3]), "r"(b0), "r"(b1));
}

// M(v)[q][p] for blade vector v[8]  (blades [1,e1,e2,e12,e3,e13,e23,e123])
__device__ __forceinline__ void pauli_entry(const float* v, int q, int p,
                                            float* re, float* im) {
    if (q == 0) {
        if (p == 0) { *re = v[0] + v[4]; *im = v[3] + v[7]; }
        else        { *re = v[1] - v[5]; *im = -v[2] + v[6]; }
    } else {
        if (p == 0) { *re = v[1] + v[5]; *im = v[2] + v[6]; }
        else        { *re = v[0] - v[4]; *im = -v[3] + v[7]; }
    }
}

__device__ __forceinline__ void flag_wait(const unsigned* f, unsigned tgt) {
    unsigned v;
    do {
        asm volatile("ld.volatile.global.u32 %0, [%1];" : "=r"(v) : "l"(f));
    } while ((int)(v - tgt) < 0);
}

// ---------------- build / init ----------------
__global__ void build_wf(const float* __restrict__ A) {
    size_t idx = (size_t)blockIdx.x * blockDim.x + threadIdx.x;
    if (idx >= (size_t)CCF * KRF) return;
    int col = (int)(idx >> 11), k = (int)(idx & (KRF - 1));
    int m = col >> 2, pp = (col >> 1) & 1, ro = col & 1;
    int n = k >> 2, q = (k >> 1) & 1, ri = k & 1;
    const float* a = A + ((size_t)m * NDIM + n) * 8;
    float re, im;
    pauli_entry(a, q, pp, &re, &im);
    float v = (ri == 0) ? (ro == 0 ? re : im) : (ro == 0 ? -im : re);
    g_Wf[idx] = __float2half(v);
}

__global__ void build_wb(const float* __restrict__ A) {
    size_t idx = (size_t)blockIdx.x * blockDim.x + threadIdx.x;
    if (idx >= (size_t)CCB * KRB) return;
    int col = (int)(idx >> 10), k = (int)(idx & (KRB - 1));
    int n = col >> 2, qp = (col >> 1) & 1, ro = col & 1;
    int m = k >> 2, p = (k >> 1) & 1, ri = k & 1;
    const float* a = A + ((size_t)m * NDIM + n) * 8;
    float re, im;
    pauli_entry(a, qp, p, &re, &im);       // conj applied via signs below
    float v = (ri == 0) ? (ro == 0 ? re : -im) : (ro == 0 ? im : re);
    g_Wb[idx] = __float2half(v);
}

__global__ void build_yr(const float* __restrict__ y) {
    int idx = blockIdx.x * blockDim.x + threadIdx.x;
    if (idx >= 128 * CCF) return;
    int row = idx >> 10, col = idx & (CCF - 1);
    int b = row >> 1, p = row & 1;
    int m = col >> 2, pp = (col >> 1) & 1, ro = col & 1;
    const float* yv = y + ((size_t)b * MDIM + m) * 8;
    float re, im;
    pauli_entry(yv, p, pp, &re, &im);
    g_yr[idx] = ro ? im : re;
}

__global__ void init_all() {
    int idx = blockIdx.x * blockDim.x + threadIdx.x;
    if (idx < BDIM * NDIM * 8) g_xs[idx] = 0.0f;
    if (idx < 128 * KRF) {
        g_X[0][idx] = __float2half(0.0f);
        g_X[1][idx] = __float2half(0.0f);
    }
    if (idx < 32 * 32) { g_ff[idx] = 0u; g_fe[idx] = 0u; }
    if (idx < 64 * 32) { g_fb[idx] = 0u; g_fu[idx] = 0u; }
}

// ---------------- gemm: 128 rows x 32 cols, kchunk 256 (4 stages) ----------------
__device__ __forceinline__ void issue_stage(
    uint32_t sb, int buf, int tid, const __half* Xm, const __half* Wm,
    int Kdim, int c0, int kk)
{
    uint32_t base = sb + buf * BUF_BYTES;
#pragma unroll
    for (int r = 0; r < 5; r++) {
        int q = tid + (r << 8);                // 1280 16B chunks per stage
        if (q < 1280) {
            const __half* gp;
            uint32_t tb;
            int row, cc;
            if (q < 1024) {                    // A: 128 rows x 8 chunks
                row = q >> 3; cc = q & 7;
                gp = Xm + (size_t)row * Kdim + kk + cc * 8;
                tb = base;
            } else {                           // B: 32 rows x 8 chunks
                int q2 = q - 1024;
                row = q2 >> 3; cc = q2 & 7;
                gp = Wm + (size_t)(c0 + row) * Kdim + kk + cc * 8;
                tb = base + 16384;
            }
            uint32_t off = (uint32_t)((row << 7) | ((cc ^ (row & 7)) << 4));
            CP_ASYNC16(tb + off, gp);
        }
    }
    CP_COMMIT();
}

__device__ void gemm_phase(uint32_t sb, const __half* Xm, const __half* Wm,
                           float* part, int Kdim, int Cc, int c0, int ks)
{
    const int tid = threadIdx.x;
    const int k0 = ks * 256;
    const int nst = 4;

    const int warp = tid >> 5, lane = tid & 31;   // 8 warps: rows warp*16
    const int lrow = lane & 15;
    const int lhalf = lane >> 4;
    const int lsw = lrow & 7;

    float acc[4][4];
#pragma unroll
    for (int g = 0; g < 4; g++)
#pragma unroll
        for (int v = 0; v < 4; v++) acc[g][v] = 0.0f;

    issue_stage(sb, 0, tid, Xm, Wm, Kdim, c0, k0);

    for (int s = 0; s < nst; s++) {
        if (s + 1 < nst) {
            issue_stage(sb, (s + 1) & 1, tid, Xm, Wm, Kdim, c0, k0 + (s + 1) * KT);
            CP_WAIT1();
        } else {
            CP_COMMIT();
            CP_WAIT0();
        }
        __syncthreads();

        uint32_t bufb = sb + (s & 1) * BUF_BYTES;
#pragma unroll
        for (int kk = 0; kk < 4; kk++) {
            uint32_t ksel = (uint32_t)((((kk << 1) | lhalf) ^ lsw) << 4);
            uint32_t ah[4], b0[4], b1[4];
            {
                uint32_t rb = (uint32_t)((warp * 16 + lrow) << 7) + ksel;
                ldsm4(ah, bufb + rb);
            }
            {
                uint32_t rb0 = (uint32_t)(lrow << 7) + ksel;          // B rows 0..15
                uint32_t rb1 = (uint32_t)((16 + lrow) << 7) + ksel;   // B rows 16..31
                ldsm4(b0, bufb + 16384u + rb0);
                ldsm4(b1, bufb + 16384u + rb1);
            }
#pragma unroll
            for (int g = 0; g < 4; g++) {
                const uint32_t* bp = (g < 2) ? b0 : b1;
                int sel = g & 1;
                mma_fp16(acc[g], ah, bp[sel], bp[sel + 2]);
            }
        }
        __syncthreads();
    }

    const int qrow = lane >> 2, qcol2 = (lane & 3) << 1;
    float* po = part + (size_t)ks * 128 * Cc;
#pragma unroll
    for (int g = 0; g < 4; g++) {
        int row = warp * 16 + qrow;
        int col = c0 + g * 8 + qcol2;
        *reinterpret_cast<float2*>(&po[(size_t)row * Cc + col]) =
            make_float2(acc[g][0], acc[g][1]);
        *reinterpret_cast<float2*>(&po[(size_t)(row + 8) * Cc + col]) =
            make_float2(acc[g][2], acc[g][3]);
    }
}

// ---------------- persistent kernel (dataflow, oversubscribed) ----------------
__global__ __launch_bounds__(NTHREADS, 2) void ista_persist(float* __restrict__ out) {
    extern __shared__ char smem[];
    uint32_t sb = smem_u32(smem);
    const int cta = blockIdx.x;
    const int t = threadIdx.x;

    const int ct = cta & 31;       // fwd/err coltile (32 x 32cols)
    const int ks = cta >> 5;       // fwd split (8)
    const int ct2 = cta >> 2;      // bwd/upd coltile (64 x 32cols)
    const int ks2 = cta & 3;       // bwd split (4)

    for (int it = 0; it < NITER; it++) {
        const int p = it & 1;

        // ---- fwd: pf[p][ks] cols [ct*32,+32) = X[p] @ Wf-tile ----
        gemm_phase(sb, g_X[p], g_Wf, g_pf[p], KRF, CCF, ct * 32, ks);
        __syncthreads();
        if (t == 0) {
            __threadfence();
            atomicAdd(&g_ff[ct * 32], 1u);
            flag_wait(&g_ff[ct * 32], 8u * (it + 1));
            __threadfence();
        }
        __syncthreads();

        // ---- err chunk: rows [ks*16,+16), cols [ct*32,+32) ----
        {
            int row = ks * 16 + (t >> 4);
            int col = ct * 32 + (t & 15) * 2;
            float2 s = make_float2(0.f, 0.f);
#pragma unroll
            for (int q = 0; q < FWD_SPLIT; q++) {
                float2 v = *reinterpret_cast<const float2*>(
                    &g_pf[p][(size_t)q * 128 * CCF + (size_t)row * CCF + col]);
                s.x += v.x; s.y += v.y;
            }
            float2 yv = *reinterpret_cast<const float2*>(&g_yr[(size_t)row * CCF + col]);
            *reinterpret_cast<__half2*>(&g_E[p][(size_t)row * KRB + col]) =
                __floats2half2_rn(s.x - yv.x, s.y - yv.y);
        }
        __syncthreads();
        if (t == 0) {
            __threadfence();
            atomicAdd(&g_fe[ct * 32], 1u);
            // bwd needs err coltiles [ks2*8 .. +8)
#pragma unroll
            for (int j = 0; j < 8; j++)
                flag_wait(&g_fe[(ks2 * 8 + j) * 32], 8u * (it + 1));
            __threadfence();
        }
        __syncthreads();

        // ---- bwd: pb[p][ks2] cols [ct2*32,+32) = E[p] @ Wb-tile ----
        gemm_phase(sb, g_E[p], g_Wb, g_pb[p], KRB, CCB, ct2 * 32, ks2);
        __syncthreads();
        if (t == 0) {
            __threadfence();
            atomicAdd(&g_fb[ct2 * 32], 1u);
            flag_wait(&g_fb[ct2 * 32], 4u * (it + 1));
            __threadfence();
        }
        __syncthreads();

        // ---- upd chunk: b in [ks2*16,+16), n in [ct2*8,+8) ----
        if (t < 128) {
            int b = ks2 * 16 + (t >> 3);
            int n = ct2 * 8 + (t & 7);
            size_t r0 = (size_t)(2 * b) * CCB + 4 * n;
            size_t r1 = r0 + CCB;
            float4 G0 = make_float4(0.f, 0.f, 0.f, 0.f);
            float4 G1 = make_float4(0.f, 0.f, 0.f, 0.f);
#pragma unroll
            for (int q = 0; q < BWD_SPLIT; q++) {
                float4 a = *reinterpret_cast<const float4*>(
                    &g_pb[p][(size_t)q * 128 * CCB + r0]);
                float4 c = *reinterpret_cast<const float4*>(
                    &g_pb[p][(size_t)q * 128 * CCB + r1]);
                G0.x += a.x; G0.y += a.y; G0.z += a.z; G0.w += a.w;
                G1.x += c.x; G1.y += c.y; G1.z += c.z; G1.w += c.w;
            }
            float g[8];
            g[0] = 0.5f * (G0.x + G1.z);
            g[4] = 0.5f * (G0.x - G1.z);
            g[3] = 0.5f * (G0.y - G1.w);
            g[7] = 0.5f * (G0.y + G1.w);
            g[1] = 0.5f * (G0.z + G1.x);
            g[5] = 0.5f * (G1.x - G0.z);
            g[2] = 0.5f * (G1.y - G0.w);
            g[6] = 0.5f * (G0.w + G1.y);

            int idx = b * NDIM + n;
            float* xs = g_xs + (size_t)idx * 8;
            float x[8];
#pragma unroll
            for (int i = 0; i < 8; i++) {
                float xv = xs[i] - STEPF * g[i];
                float thr = (i == 0) ? 0.0f : ((i == 7) ? 0.002f : 0.001f);
                float a = fabsf(xv) - thr;
                x[i] = (a > 0.0f) ? copysignf(a, xv) : 0.0f;
                xs[i] = x[i];
            }
            const int p1 = (it + 1) & 1;
            __half2* X0 = reinterpret_cast<__half2*>(&g_X[p1][(size_t)(2 * b) * KRF + 4 * n]);
            __half2* X1 = reinterpret_cast<__half2*>(&g_X[p1][(size_t)(2 * b + 1) * KRF + 4 * n]);
            X0[0] = __floats2half2_rn(x[0] + x[4], x[3] + x[7]);
            X0[1] = __floats2half2_rn(x[1] - x[5], -x[2] + x[6]);
            X1[0] = __floats2half2_rn(x[1] + x[5], x[2] + x[6]);
            X1[1] = __floats2half2_rn(x[0] - x[4], -x[3] + x[7]);

            if (it == NITER - 1) {
                float4* po = reinterpret_cast<float4*>(&out[(size_t)idx * 8]);
                po[0] = make_float4(x[0], x[1], x[2], x[3]);
                po[1] = make_float4(x[4], x[5], x[6], x[7]);
            }
        }
        __syncthreads();
        if (t == 0) {
            __threadfence();
            atomicAdd(&g_fu[ct2 * 32], 1u);
            if (it + 1 < NITER) {
                // next fwd needs upd coltiles [ks*8 .. +8)
#pragma unroll
                for (int j = 0; j < 8; j++)
                    flag_wait(&g_fu[(ks * 8 + j) * 32], 4u * (it + 1));
                __threadfence();
            }
        }
        __syncthreads();
    }
}

// ---------------- host ----------------
extern "C" void kernel_launch(void* const* d_in, const int* in_sizes, int n_in,
                              void* d_out, int out_size)
{
    const float* y = (const float*)d_in[0];
    const float* A = (const float*)d_in[1];
    if (n_in >= 2 && in_sizes[0] > in_sizes[1]) {
        const float* t = y; y = A; A = t;
    }

    cudaFuncSetAttribute(ista_persist, cudaFuncAttributeMaxDynamicSharedMemorySize, SMEM_TOTAL);

    build_wf<<<(int)(((size_t)CCF * KRF + 255) / 256), 256>>>(A);
    build_wb<<<(int)(((size_t)CCB * KRB + 255) / 256), 256>>>(A);
    build_yr<<<(128 * CCF + 255) / 256, 256>>>(y);
    init_all<<<(128 * KRF + 255) / 256, 256>>>();

    ista_persist<<<GRID, NTHREADS, SMEM_TOTAL>>>((float*)d_out);
}